// round 6
// baseline (speedup 1.0000x reference)
#include <cuda_runtime.h>
#include <cstdint>

// Problem constants (from reference setup)
#define B_   32
#define S_   512
#define D_   256
#define TT   128          // frames per block tile
#define KF   16           // fast-path cap on K
#define EPSF 1e-6f
#define INV_SQRT_2PI 0.3989422804014327f

// shared: fast path uses wsm[KF*TT]=2048 floats + params at 2048..
// fallback uses fc/fis/fcf/fid/wf = 5*512 = 2560 floats + sdur at 2560..3072
#define SMEM_F 3136

// dtype-agnostic integer load (inputs may be int32 or int64 depending on jax x64)
__device__ __forceinline__ long long load_i(const void* p, int idx, bool is64) {
    return is64 ? ((const long long*)p)[idx] : (long long)((const int*)p)[idx];
}

// ---- phase 2: thread owns one d; weights pre-normalized & pre-masked ----
template<int KC>
__device__ __forceinline__ void phase2(const float* __restrict__ wsm,
                                       const float* __restrict__ embed,
                                       const int*   __restrict__ s_id,
                                       float* __restrict__ outb,  // out + (b*T+t0)*D + d
                                       int d, int frames)
{
    float es[KC];
    #pragma unroll
    for (int s = 0; s < KC; s++)
        es[s] = embed[(size_t)s_id[s] * D_ + d];

    if (frames == TT) {
        #pragma unroll 4
        for (int tg = 0; tg < TT; tg += 4) {
            float a0 = 0.f, a1 = 0.f, a2 = 0.f, a3 = 0.f;
            #pragma unroll
            for (int s = 0; s < KC; s++) {
                float4 wv = *reinterpret_cast<const float4*>(wsm + s * TT + tg); // broadcast
                a0 = fmaf(wv.x, es[s], a0);
                a1 = fmaf(wv.y, es[s], a1);
                a2 = fmaf(wv.z, es[s], a2);
                a3 = fmaf(wv.w, es[s], a3);
            }
            outb[(size_t)(tg + 0) * D_] = a0;
            outb[(size_t)(tg + 1) * D_] = a1;
            outb[(size_t)(tg + 2) * D_] = a2;
            outb[(size_t)(tg + 3) * D_] = a3;
        }
    } else {
        for (int t = 0; t < frames; t++) {
            float a = 0.f;
            #pragma unroll
            for (int s = 0; s < KC; s++)
                a = fmaf(wsm[s * TT + t], es[s], a);
            outb[(size_t)t * D_] = a;
        }
    }
}

// ---------------- single fused kernel ----------------
__global__ __launch_bounds__(256)
void gauss_fused_kernel(const void* __restrict__ text,
                        const void* __restrict__ durs,
                        const float* __restrict__ embed,
                        float* __restrict__ out, int T)
{
    __shared__ __align__(16) float smem[SMEM_F];
    __shared__ int sK, stot;

    const int b   = blockIdx.y;
    const int t0  = blockIdx.x * TT;
    const int tid = threadIdx.x;
    if (t0 >= T) return;

    // dtype detection: text values are all in [1,256); if int64 (LE), the
    // second 32-bit word is the high half of text[0] == 0; if int32 it's
    // text[0][1] >= 1.
    const bool is64 = (((const int*)text)[1] == 0);

    float* wsm  = smem;               // [KF][TT] fast-path weights (s-major)
    float* s_c  = smem + KF * TT;     // [KF]
    float* s_is = s_c  + KF;          // [KF]
    float* s_cf = s_is + KF;          // [KF]
    int*   s_id = (int*)(s_cf + KF);  // [KF]

    // ---- warp-0 prologue: ballot K detection + shfl scan of params ----
    if (tid < 32) {
        const int lane = tid;
        long long dv = load_i(durs, b * S_ + lane, is64);
        unsigned  m  = __ballot_sync(0xffffffffu, dv == 0);
        int K;
        if (m) {
            K = __ffs(m) - 1;
        } else {
            K = S_;
            for (int base = 32; base < S_; base += 32) {
                long long d2 = load_i(durs, b * S_ + base + lane, is64);
                unsigned  m2 = __ballot_sync(0xffffffffu, d2 == 0);
                if (m2) { K = base + __ffs(m2) - 1; break; }
            }
        }
        // inclusive scan over first 32 durs (valid whenever K <= 32)
        float df = (lane < K) ? (float)dv : 0.0f;
        float incl = df;
        #pragma unroll
        for (int off = 1; off < 32; off <<= 1) {
            float n = __shfl_up_sync(0xffffffffu, incl, off);
            if (lane >= off) incl += n;
        }
        float excl  = incl - df;
        float total = __shfl_sync(0xffffffffu, incl, 31);
        if (K <= KF && lane < K) {
            float sig  = 0.5f * df + EPSF;
            s_c [lane] = 0.5f * df + excl;
            s_is[lane] = 1.0f / sig;
            s_cf[lane] = INV_SQRT_2PI / sig;
            s_id[lane] = (int)load_i(text, b * S_ + lane, is64);
        }
        if (lane == 0) { sK = K; stot = (int)total; }
    }
    __syncthreads();
    const int K = sK;
    int frames = T - t0; if (frames > TT) frames = TT;

    if (K == 0) {
        // all frames invalid -> last (PAD) column has zero embedding -> zeros
        float* outb = out + ((size_t)b * T + t0) * D_ + tid;
        for (int t = 0; t < frames; t++) outb[(size_t)t * D_] = 0.0f;
        return;
    }

    if (K <= KF) {
        // ---- phase 1: gaussian weights, s-major [s][TT] ----
        const int items = K * TT;
        for (int idx = tid; idx < items; idx += 256) {
            int s = idx >> 7;                 // TT == 128
            int t = idx & (TT - 1);
            float tt = (float)(t0 + t) + 0.5f;
            float z  = (tt - s_c[s]) * s_is[s];
            wsm[idx] = s_cf[s] * __expf(-0.5f * z * z);
        }
        __syncthreads();

        // ---- fold normalization + time-invalid mask in place ----
        if (tid < TT) {
            float den = EPSF;
            for (int s = 0; s < K; s++) den += wsm[s * TT + tid];
            float r = 1.0f / den;
            if (t0 + tid >= stot) r = 0.0f;   // invalid frames -> zeros (pad col embed==0)
            for (int s = 0; s < K; s++) wsm[s * TT + tid] *= r;
        }
        __syncthreads();

        // ---- phase 2 ----
        const int d = tid;
        float* outb = out + ((size_t)b * T + t0) * D_ + d;
        switch (K) {
            case 1:  phase2<1 >(wsm, embed, s_id, outb, d, frames); break;
            case 2:  phase2<2 >(wsm, embed, s_id, outb, d, frames); break;
            case 3:  phase2<3 >(wsm, embed, s_id, outb, d, frames); break;
            case 4:  phase2<4 >(wsm, embed, s_id, outb, d, frames); break;
            case 5:  phase2<5 >(wsm, embed, s_id, outb, d, frames); break;
            case 6:  phase2<6 >(wsm, embed, s_id, outb, d, frames); break;
            case 7:  phase2<7 >(wsm, embed, s_id, outb, d, frames); break;
            case 8:  phase2<8 >(wsm, embed, s_id, outb, d, frames); break;
            case 9:  phase2<9 >(wsm, embed, s_id, outb, d, frames); break;
            case 10: phase2<10>(wsm, embed, s_id, outb, d, frames); break;
            case 11: phase2<11>(wsm, embed, s_id, outb, d, frames); break;
            case 12: phase2<12>(wsm, embed, s_id, outb, d, frames); break;
            case 13: phase2<13>(wsm, embed, s_id, outb, d, frames); break;
            case 14: phase2<14>(wsm, embed, s_id, outb, d, frames); break;
            case 15: phase2<15>(wsm, embed, s_id, outb, d, frames); break;
            default: phase2<16>(wsm, embed, s_id, outb, d, frames); break;
        }
    } else {
        // ---- general fallback (K > KF): rare, correct for any K <= S_ ----
        float* fc   = smem;                  // [S_]
        float* fis  = smem + S_;             // [S_]
        float* fcf  = smem + 2 * S_;         // [S_]
        int*   fid  = (int*)(smem + 3 * S_); // [S_]
        float* wf   = smem + 4 * S_;         // [S_]
        float* sdur = smem + 5 * S_;         // [S_] -- needs SMEM_F >= 3072

        for (int s = tid; s < S_; s += 256)
            sdur[s] = (float)load_i(durs, b * S_ + s, is64);
        __syncthreads();
        if (tid == 0) {
            float cum = 0.0f;
            for (int k = 0; k < K; k++) {
                float df  = sdur[k];
                float sig = 0.5f * df + EPSF;
                fc [k] = 0.5f * df + cum;
                fis[k] = 1.0f / sig;
                fcf[k] = INV_SQRT_2PI / sig;
                cum += df;
            }
            stot = (int)cum;
        }
        for (int k = tid; k < K; k += 256)
            fid[k] = (int)load_i(text, b * S_ + k, is64);
        __syncthreads();
        const int total = stot;

        const int d = tid;
        for (int t = 0; t < TT; t++) {
            int tabs = t0 + t;
            if (tabs >= T) break;
            for (int s = tid; s < K; s += 256) {
                float tt = (float)tabs + 0.5f;
                float z  = (tt - fc[s]) * fis[s];
                wf[s] = fcf[s] * __expf(-0.5f * z * z);
            }
            __syncthreads();
            float den = EPSF;
            for (int s = 0; s < K; s++) den += wf[s];
            float acc = 0.f;
            for (int s = 0; s < K; s++) acc += wf[s] * embed[fid[s] * D_ + d];
            out[((size_t)b * T + tabs) * D_ + d] = (tabs < total) ? acc / den : 0.0f;
            __syncthreads();
        }
    }
}

// ---------------- launcher: ONE kernel node ----------------
extern "C" void kernel_launch(void* const* d_in, const int* in_sizes, int n_in,
                              void* d_out, int out_size)
{
    const void*  text  = d_in[0];                 // int32 or int64, detected on-device
    const void*  durs  = d_in[1];
    const float* embed = (const float*)d_in[2];
    float*       out   = (float*)d_out;

    int T = out_size / (B_ * D_);                 // derive T from output size

    dim3 grid((T + TT - 1) / TT, B_);
    gauss_fused_kernel<<<grid, 256>>>(text, durs, embed, out, T);
}

// round 9
// speedup vs baseline: 1.0296x; 1.0296x over previous
#include <cuda_runtime.h>
#include <cstdint>

// Problem constants (from reference setup)
#define B_    32
#define S_    512
#define D_    256
#define TT    256         // frames per block tile (512 blocks -> single wave)
#define KFAST 10          // fast-path cap on K
#define EPSF  1e-6f
#define INV_SQRT_2PI 0.3989422804014327f

// shared layout (floats)
#define OFF_W   0                      // [KFAST*TT]  weights, s-major      (2560)
#define OFF_E   (OFF_W + KFAST * TT)   // [KFAST*D_]  embedding rows        (2560)
#define OFF_DUR (OFF_E + KFAST * D_)   // [S_]        durations as float    (512)
#define OFF_P   (OFF_DUR + S_)         // params: c, is, cf, id  (4*KFAST -> pad 64)
#define SMEM_F  (OFF_P + 64)
// fallback (K > KFAST) aliases the wsm/esm region: fc/fis/fcf/fid/wf = 5*S_ = 2560

// dtype-agnostic integer load (inputs may be int32 or int64 depending on jax x64)
__device__ __forceinline__ long long load_i(const void* p, int idx, bool is64) {
    return is64 ? ((const long long*)p)[idx] : (long long)((const int*)p)[idx];
}

// ---- phase 2: thread owns one d; weights pre-normalized & pre-masked ----
template<int KC>
__device__ __forceinline__ void phase2(const float* __restrict__ wsm,
                                       const float* __restrict__ esm,
                                       float* __restrict__ outb,  // out+(b*T+t0)*D+d
                                       int d, int frames)
{
    float es[KC];
    #pragma unroll
    for (int s = 0; s < KC; s++) es[s] = esm[s * D_ + d];

    if (frames == TT) {
        for (int tg = 0; tg < TT; tg += 4) {
            float a0 = 0.f, a1 = 0.f, a2 = 0.f, a3 = 0.f;
            #pragma unroll
            for (int s = 0; s < KC; s++) {
                float4 wv = *reinterpret_cast<const float4*>(wsm + s * TT + tg); // broadcast
                a0 = fmaf(wv.x, es[s], a0);
                a1 = fmaf(wv.y, es[s], a1);
                a2 = fmaf(wv.z, es[s], a2);
                a3 = fmaf(wv.w, es[s], a3);
            }
            outb[(size_t)(tg + 0) * D_] = a0;
            outb[(size_t)(tg + 1) * D_] = a1;
            outb[(size_t)(tg + 2) * D_] = a2;
            outb[(size_t)(tg + 3) * D_] = a3;
        }
    } else {
        for (int t = 0; t < frames; t++) {
            float a = 0.f;
            #pragma unroll
            for (int s = 0; s < KC; s++)
                a = fmaf(wsm[s * TT + t], es[s], a);
            outb[(size_t)t * D_] = a;
        }
    }
}

// ---------------- single fused kernel ----------------
__global__ __launch_bounds__(256)
void gauss_fused_kernel(const void* __restrict__ text,
                        const void* __restrict__ durs,
                        const float* __restrict__ embed,
                        float* __restrict__ out, int T)
{
    __shared__ __align__(16) float smem[SMEM_F];
    __shared__ int sK, stot;

    const int b   = blockIdx.y;
    const int t0  = blockIdx.x * TT;
    const int tid = threadIdx.x;
    if (t0 >= T) return;

    // dtype detection: text values are all in [1,256); if int64 (LE), the
    // second 32-bit word is the high half of text[0] == 0; if int32 it's
    // text[0][1] >= 1.
    const bool is64 = (((const int*)text)[1] == 0);

    float* wsm  = smem + OFF_W;      // [KFAST][TT]
    float* esm  = smem + OFF_E;      // [KFAST][D_]
    float* sdur = smem + OFF_DUR;    // [S_]
    float* s_c  = smem + OFF_P;      // [KFAST]
    float* s_is = s_c  + KFAST;
    float* s_cf = s_is + KFAST;
    int*   s_id = (int*)(s_cf + KFAST);

    // ---- parallel dur load + K detection (nonzero durs form a prefix) ----
    if (tid == 0) sK = S_;
    __syncthreads();
    for (int s = tid; s < S_; s += 256) {
        long long dv = load_i(durs, b * S_ + s, is64);
        sdur[s] = (float)dv;
        if (dv == 0) atomicMin(&sK, s);
    }
    __syncthreads();
    const int K = sK;
    int frames = T - t0; if (frames > TT) frames = TT;

    // ---- warp-0 parallel param scan (valid for K <= 32; used for K <= KFAST) ----
    if (K <= KFAST && tid < 32) {
        const int lane = tid;
        float df = (lane < K) ? sdur[lane] : 0.0f;
        float incl = df;
        #pragma unroll
        for (int off = 1; off < 32; off <<= 1) {
            float n = __shfl_up_sync(0xffffffffu, incl, off);
            if (lane >= off) incl += n;
        }
        float excl  = incl - df;
        float total = __shfl_sync(0xffffffffu, incl, 31);
        if (lane < K) {
            float sig  = 0.5f * df + EPSF;
            s_c [lane] = 0.5f * df + excl;
            s_is[lane] = 1.0f / sig;
            s_cf[lane] = INV_SQRT_2PI / sig;
            s_id[lane] = (int)load_i(text, b * S_ + lane, is64);
        }
        if (lane == 0) stot = (int)total;
    }
    __syncthreads();

    if (K == 0) {
        // all frames invalid -> last (PAD) column has zero embedding -> zeros
        float* outb = out + ((size_t)b * T + t0) * D_ + tid;
        for (int t = 0; t < frames; t++) outb[(size_t)t * D_] = 0.0f;
        return;
    }

    if (K <= KFAST) {
        // ---- phase 1: gaussian weights, s-major [s][TT] ----
        const int items = K * TT;
        for (int idx = tid; idx < items; idx += 256) {
            int s = idx >> 8;                 // TT == 256
            int t = idx & (TT - 1);
            float tt = (float)(t0 + t) + 0.5f;
            float z  = (tt - s_c[s]) * s_is[s];
            wsm[idx] = s_cf[s] * __expf(-0.5f * z * z);
        }
        // ---- stage the K embedding rows into shared ----
        for (int idx = tid; idx < K * D_; idx += 256) {
            int s = idx >> 8;                 // D_ == 256
            esm[idx] = embed[(size_t)s_id[s] * D_ + (idx & (D_ - 1))];
        }
        __syncthreads();

        // ---- fold normalization + time-invalid mask into wsm in place ----
        {   // TT == blockDim: every thread owns one frame
            float den = EPSF;
            for (int s = 0; s < K; s++) den += wsm[s * TT + tid];
            float r = 1.0f / den;
            if (t0 + tid >= stot) r = 0.0f;   // invalid frames -> zeros
            for (int s = 0; s < K; s++) wsm[s * TT + tid] *= r;
        }
        __syncthreads();

        // ---- phase 2 ----
        const int d = tid;
        float* outb = out + ((size_t)b * T + t0) * D_ + d;
        switch (K) {
            case 1:  phase2<1 >(wsm, esm, outb, d, frames); break;
            case 2:  phase2<2 >(wsm, esm, outb, d, frames); break;
            case 3:  phase2<3 >(wsm, esm, outb, d, frames); break;
            case 4:  phase2<4 >(wsm, esm, outb, d, frames); break;
            case 5:  phase2<5 >(wsm, esm, outb, d, frames); break;
            case 6:  phase2<6 >(wsm, esm, outb, d, frames); break;
            case 7:  phase2<7 >(wsm, esm, outb, d, frames); break;
            case 8:  phase2<8 >(wsm, esm, outb, d, frames); break;
            case 9:  phase2<9 >(wsm, esm, outb, d, frames); break;
            default: phase2<10>(wsm, esm, outb, d, frames); break;
        }
    } else {
        // ---- general fallback (K > KFAST): rare, correct for any K <= S_ ----
        float* fc  = smem;                  // [S_]
        float* fis = smem + S_;             // [S_]
        float* fcf = smem + 2 * S_;         // [S_]
        int*   fid = (int*)(smem + 3 * S_); // [S_]
        float* wf  = smem + 4 * S_;         // [S_]  (5*S_ = 2560 <= OFF_DUR ✓)

        if (tid == 0) {
            float cum = 0.0f;
            for (int k = 0; k < K; k++) {
                float df  = sdur[k];
                float sig = 0.5f * df + EPSF;
                fc [k] = 0.5f * df + cum;
                fis[k] = 1.0f / sig;
                fcf[k] = INV_SQRT_2PI / sig;
                cum += df;
            }
            stot = (int)cum;
        }
        for (int k = tid; k < K; k += 256)
            fid[k] = (int)load_i(text, b * S_ + k, is64);
        __syncthreads();
        const int total = stot;

        const int d = tid;
        for (int t = 0; t < frames; t++) {
            int tabs = t0 + t;
            for (int s = tid; s < K; s += 256) {
                float tt = (float)tabs + 0.5f;
                float z  = (tt - fc[s]) * fis[s];
                wf[s] = fcf[s] * __expf(-0.5f * z * z);
            }
            __syncthreads();
            float den = EPSF;
            for (int s = 0; s < K; s++) den += wf[s];
            float acc = 0.f;
            for (int s = 0; s < K; s++) acc += wf[s] * embed[(size_t)fid[s] * D_ + d];
            out[((size_t)b * T + tabs) * D_ + d] = (tabs < total) ? acc / den : 0.0f;
            __syncthreads();
        }
    }
}

// ---------------- launcher: ONE kernel node ----------------
extern "C" void kernel_launch(void* const* d_in, const int* in_sizes, int n_in,
                              void* d_out, int out_size)
{
    const void*  text  = d_in[0];                 // int32 or int64, detected on-device
    const void*  durs  = d_in[1];
    const float* embed = (const float*)d_in[2];
    float*       out   = (float*)d_out;

    int T = out_size / (B_ * D_);                 // derive T from output size

    dim3 grid((T + TT - 1) / TT, B_);
    gauss_fused_kernel<<<grid, 256>>>(text, durs, embed, out, T);
}

// round 12
// speedup vs baseline: 1.7728x; 1.7218x over previous
#include <cuda_runtime.h>
#include <cstdint>

// Problem constants (from reference setup)
#define B_   32
#define S_   512
#define D_   256
#define KSM  12           // fast-path cap on tokens kept in shared (smem 21KB -> 6 blocks/SM)
#define TT   128          // frames per block tile
#define EPSF 1e-6f
#define INV_SQRT_2PI 0.3989422804014327f

// shared layout (floats), one contiguous block so the fallback can alias it
#define OFF_W    0                        // [KSM*TT]  weights, s-major
#define OFF_E    (OFF_W  + KSM * TT)      // [KSM*D_]  embedding rows
#define OFF_DEN  (OFF_E  + KSM * D_)      // [TT]      reciprocal denominators
#define OFF_DUR  (OFF_DEN + TT)           // [S_]      durations (float)
#define OFF_C    (OFF_DUR + S_)           // [KSM]
#define OFF_IS   (OFF_C   + KSM)          // [KSM]
#define OFF_CF   (OFF_IS  + KSM)          // [KSM]
#define OFF_ID   (OFF_CF  + KSM)          // [KSM] (ints)
#define SMEM_F   (OFF_ID  + KSM)

// dtype-agnostic integer load (inputs may be int32 or int64 depending on jax x64)
__device__ __forceinline__ long long load_i(const void* p, int idx, bool is64) {
    return is64 ? ((const long long*)p)[idx] : (long long)((const int*)p)[idx];
}

// ---- templated phase-2 inner loop: K embedding values live in registers ----
template<int KC>
__device__ __forceinline__ void phase2(const float* __restrict__ wsm,
                                       const float* __restrict__ esm,
                                       const float* __restrict__ sden,
                                       float* __restrict__ outb,
                                       int t0, int total, int T, int d)
{
    float es[KC];
    #pragma unroll
    for (int s = 0; s < KC; s++) es[s] = esm[s * D_ + d];

    for (int tg = 0; tg < TT; tg += 4) {
        float a0 = 0.f, a1 = 0.f, a2 = 0.f, a3 = 0.f;
        #pragma unroll
        for (int s = 0; s < KC; s++) {
            float4 wv = *reinterpret_cast<const float4*>(wsm + s * TT + tg); // broadcast
            a0 = fmaf(wv.x, es[s], a0);
            a1 = fmaf(wv.y, es[s], a1);
            a2 = fmaf(wv.z, es[s], a2);
            a3 = fmaf(wv.w, es[s], a3);
        }
        int t = t0 + tg;
        if (t + 3 < T) {
            outb[(size_t)(tg + 0) * D_] = (t + 0 < total) ? a0 * sden[tg + 0] : 0.0f;
            outb[(size_t)(tg + 1) * D_] = (t + 1 < total) ? a1 * sden[tg + 1] : 0.0f;
            outb[(size_t)(tg + 2) * D_] = (t + 2 < total) ? a2 * sden[tg + 2] : 0.0f;
            outb[(size_t)(tg + 3) * D_] = (t + 3 < total) ? a3 * sden[tg + 3] : 0.0f;
        } else {
            float av[4] = {a0, a1, a2, a3};
            for (int i = 0; i < 4; i++)
                if (t + i < T)
                    outb[(size_t)(tg + i) * D_] = (t + i < total) ? av[i] * sden[tg + i] : 0.0f;
        }
    }
}

// generic (register-hoist not possible): used for 10 < K <= KSM
__device__ __forceinline__ void phase2_gen(const float* __restrict__ wsm,
                                           const float* __restrict__ esm,
                                           const float* __restrict__ sden,
                                           float* __restrict__ outb,
                                           int t0, int total, int T, int d, int K)
{
    for (int tg = 0; tg < TT; tg += 4) {
        float a0 = 0.f, a1 = 0.f, a2 = 0.f, a3 = 0.f;
        #pragma unroll 4
        for (int s = 0; s < K; s++) {
            float  es = esm[s * D_ + d];
            float4 wv = *reinterpret_cast<const float4*>(wsm + s * TT + tg);
            a0 = fmaf(wv.x, es, a0);
            a1 = fmaf(wv.y, es, a1);
            a2 = fmaf(wv.z, es, a2);
            a3 = fmaf(wv.w, es, a3);
        }
        int t = t0 + tg;
        if (t + 3 < T) {
            outb[(size_t)(tg + 0) * D_] = (t + 0 < total) ? a0 * sden[tg + 0] : 0.0f;
            outb[(size_t)(tg + 1) * D_] = (t + 1 < total) ? a1 * sden[tg + 1] : 0.0f;
            outb[(size_t)(tg + 2) * D_] = (t + 2 < total) ? a2 * sden[tg + 2] : 0.0f;
            outb[(size_t)(tg + 3) * D_] = (t + 3 < total) ? a3 * sden[tg + 3] : 0.0f;
        } else {
            float av[4] = {a0, a1, a2, a3};
            for (int i = 0; i < 4; i++)
                if (t + i < T)
                    outb[(size_t)(tg + i) * D_] = (t + i < total) ? av[i] * sden[tg + i] : 0.0f;
        }
    }
}

// ---------------- single fused kernel ----------------
__global__ __launch_bounds__(256, 6)
void gauss_fused_kernel(const void* __restrict__ text,
                        const void* __restrict__ durs,
                        const float* __restrict__ embed,
                        float* __restrict__ out, int T)
{
    __shared__ float smem[SMEM_F];
    __shared__ int   sK, stot;
    float* wsm  = smem + OFF_W;
    float* esm  = smem + OFF_E;
    float* sden = smem + OFF_DEN;
    float* sdur = smem + OFF_DUR;
    float* s_c  = smem + OFF_C;
    float* s_is = smem + OFF_IS;
    float* s_cf = smem + OFF_CF;
    int*   s_id = (int*)(smem + OFF_ID);

    const int b   = blockIdx.y;
    const int t0  = blockIdx.x * TT;
    const int tid = threadIdx.x;
    if (t0 >= T) return;

    // dtype detection: text values are all in [1,256); if int64 (LE), the
    // second 32-bit word is the high half of text[0] == 0; if int32 it's
    // text[0][1] >= 1.
    const bool is64 = (((const int*)text)[1] == 0);

    // ---- load durations, find K (nonzero durs form a prefix) ----
    if (tid == 0) sK = S_;
    __syncthreads();
    for (int s = tid; s < S_; s += 256) {
        long long dv = load_i(durs, b * S_ + s, is64);
        sdur[s] = (float)dv;
        if (dv == 0) atomicMin(&sK, s);
    }
    __syncthreads();
    const int K = sK;

    if (K <= KSM) {
        // ---- serial param scan over the tiny prefix (from shared) ----
        if (tid == 0) {
            float cum = 0.0f;
            for (int k = 0; k < K; k++) {
                float df  = sdur[k];
                float sig = 0.5f * df + EPSF;
                s_c [k] = 0.5f * df + cum;
                s_is[k] = 1.0f / sig;
                s_cf[k] = INV_SQRT_2PI / sig;
                cum += df;
            }
            stot = (int)cum;
        }
        if (tid < K) s_id[tid] = (int)load_i(text, b * S_ + tid, is64);
        __syncthreads();

        // ---- phase 1: gaussian weights for the tile, s-major in shared ----
        const int items = K * TT;
        for (int idx = tid; idx < items; idx += 256) {
            int s = idx >> 7;                 // TT == 128
            int t = idx & (TT - 1);
            float tt = (float)(t0 + t) + 0.5f;
            float z  = (tt - s_c[s]) * s_is[s];
            wsm[idx] = s_cf[s] * __expf(-0.5f * z * z);
        }
        // ---- preload the K embedding rows into shared ----
        for (int idx = tid; idx < K * D_; idx += 256) {
            int s = idx >> 8;                 // D_ == 256
            esm[idx] = embed[s_id[s] * D_ + (idx & (D_ - 1))];
        }
        __syncthreads();

        // ---- per-frame reciprocal denominator ----
        if (tid < TT) {
            float den = EPSF;
            for (int s = 0; s < K; s++) den += wsm[s * TT + tid];
            sden[tid] = 1.0f / den;
        }
        __syncthreads();

        const int total = stot;
        const int d = tid;
        float* outb = out + ((size_t)b * T + t0) * D_ + d;
        switch (K) {
            case 1:  phase2<1 >(wsm, esm, sden, outb, t0, total, T, d); break;
            case 2:  phase2<2 >(wsm, esm, sden, outb, t0, total, T, d); break;
            case 3:  phase2<3 >(wsm, esm, sden, outb, t0, total, T, d); break;
            case 4:  phase2<4 >(wsm, esm, sden, outb, t0, total, T, d); break;
            case 5:  phase2<5 >(wsm, esm, sden, outb, t0, total, T, d); break;
            case 6:  phase2<6 >(wsm, esm, sden, outb, t0, total, T, d); break;
            case 7:  phase2<7 >(wsm, esm, sden, outb, t0, total, T, d); break;
            case 8:  phase2<8 >(wsm, esm, sden, outb, t0, total, T, d); break;
            case 9:  phase2<9 >(wsm, esm, sden, outb, t0, total, T, d); break;
            case 10: phase2<10>(wsm, esm, sden, outb, t0, total, T, d); break;
            case 0:  phase2<1 >(wsm, esm, sden, outb, t0, 0,     T, d); break; // K==0: all invalid -> zeros
            default: phase2_gen(wsm, esm, sden, outb, t0, total, T, d, K); break;
        }
    } else {
        // ---- general fallback (K > KSM): alias the big shared region ----
        float* fc  = wsm;            // [S_]
        float* fis = wsm + S_;       // [S_]
        float* fcf = wsm + 2 * S_;   // [S_]
        int*   fid = (int*)(wsm + 3 * S_); // [S_]
        float* wf  = wsm + 4 * S_;   // [S_]   (5*S_ = 2560 <= KSM*(TT+D_) = 4608)

        if (tid == 0) {
            float cum = 0.0f;
            for (int k = 0; k < K; k++) {
                float df  = sdur[k];
                float sig = 0.5f * df + EPSF;
                fc [k] = 0.5f * df + cum;
                fis[k] = 1.0f / sig;
                fcf[k] = INV_SQRT_2PI / sig;
                cum += df;
            }
            stot = (int)cum;
        }
        for (int k = tid; k < K; k += 256)
            fid[k] = (int)load_i(text, b * S_ + k, is64);
        __syncthreads();
        const int total = stot;

        const int d = tid;
        for (int t = 0; t < TT; t++) {
            int tabs = t0 + t;
            if (tabs >= T) break;
            for (int s = tid; s < K; s += 256) {
                float tt = (float)tabs + 0.5f;
                float z  = (tt - fc[s]) * fis[s];
                wf[s] = fcf[s] * __expf(-0.5f * z * z);
            }
            __syncthreads();
            float den = EPSF;
            for (int s = 0; s < K; s++) den += wf[s];
            float acc = 0.f;
            for (int s = 0; s < K; s++) acc += wf[s] * embed[fid[s] * D_ + d];
            out[((size_t)b * T + tabs) * D_ + d] = (tabs < total) ? acc / den : 0.0f;
            __syncthreads();
        }
    }
}

// ---------------- launcher: ONE kernel node ----------------
extern "C" void kernel_launch(void* const* d_in, const int* in_sizes, int n_in,
                              void* d_out, int out_size)
{
    const void*  text  = d_in[0];                 // int32 or int64, detected on-device
    const void*  durs  = d_in[1];
    const float* embed = (const float*)d_in[2];
    float*       out   = (float*)d_out;

    int T = out_size / (B_ * D_);                 // derive T from output size

    dim3 grid((T + TT - 1) / TT, B_);
    gauss_fused_kernel<<<grid, 256>>>(text, durs, embed, out, T);
}

// round 13
// speedup vs baseline: 1.8049x; 1.0181x over previous
#include <cuda_runtime.h>
#include <cstdint>

// Problem constants (from reference setup)
#define B_   32
#define S_   512
#define D_   256
#define KSM  30           // fast-path cap on tokens kept in shared
#define TT   128          // frames per block tile
#define EPSF 1e-6f
#define INV_SQRT_2PI 0.3989422804014327f

// shared layout (floats), one contiguous block so the fallback can alias it
#define OFF_W    0                        // [KSM*TT]  weights, s-major
#define OFF_E    (OFF_W  + KSM * TT)      // [KSM*D_]  embedding rows
#define OFF_DUR  (OFF_E  + KSM * D_)      // [S_]      durations (float)
#define OFF_C    (OFF_DUR + S_)           // [KSM]
#define OFF_IS   (OFF_C   + KSM)          // [KSM]
#define OFF_CF   (OFF_IS  + KSM)          // [KSM]
#define OFF_ID   (OFF_CF  + KSM)          // [KSM] (ints)
#define SMEM_F   (OFF_ID  + KSM)

// dtype-agnostic integer load (inputs may be int32 or int64 depending on jax x64)
__device__ __forceinline__ long long load_i(const void* p, int idx, bool is64) {
    return is64 ? ((const long long*)p)[idx] : (long long)((const int*)p)[idx];
}

// ---- templated phase-2 inner loop: K embedding values live in registers ----
// wsm is already normalized and invalid-frame-zeroed: loop is pure LDS+FMA+STG.
template<int KC>
__device__ __forceinline__ void phase2(const float* __restrict__ wsm,
                                       const float* __restrict__ esm,
                                       float* __restrict__ outb,
                                       int t0, int T, int d)
{
    float es[KC];
    #pragma unroll
    for (int s = 0; s < KC; s++) es[s] = esm[s * D_ + d];

    if (t0 + TT <= T) {
        for (int tg = 0; tg < TT; tg += 4) {
            float a0 = 0.f, a1 = 0.f, a2 = 0.f, a3 = 0.f;
            #pragma unroll
            for (int s = 0; s < KC; s++) {
                float4 wv = *reinterpret_cast<const float4*>(wsm + s * TT + tg); // broadcast
                a0 = fmaf(wv.x, es[s], a0);
                a1 = fmaf(wv.y, es[s], a1);
                a2 = fmaf(wv.z, es[s], a2);
                a3 = fmaf(wv.w, es[s], a3);
            }
            outb[(size_t)(tg + 0) * D_] = a0;
            outb[(size_t)(tg + 1) * D_] = a1;
            outb[(size_t)(tg + 2) * D_] = a2;
            outb[(size_t)(tg + 3) * D_] = a3;
        }
    } else {
        int frames = T - t0;
        for (int t = 0; t < frames; t++) {
            float a = 0.f;
            #pragma unroll
            for (int s = 0; s < KC; s++)
                a = fmaf(wsm[s * TT + t], es[s], a);
            outb[(size_t)t * D_] = a;
        }
    }
}

// generic (register-hoist not possible): used for 10 < K <= KSM
__device__ __forceinline__ void phase2_gen(const float* __restrict__ wsm,
                                           const float* __restrict__ esm,
                                           float* __restrict__ outb,
                                           int t0, int T, int d, int K)
{
    for (int tg = 0; tg < TT; tg += 4) {
        float a0 = 0.f, a1 = 0.f, a2 = 0.f, a3 = 0.f;
        #pragma unroll 4
        for (int s = 0; s < K; s++) {
            float  es = esm[s * D_ + d];
            float4 wv = *reinterpret_cast<const float4*>(wsm + s * TT + tg);
            a0 = fmaf(wv.x, es, a0);
            a1 = fmaf(wv.y, es, a1);
            a2 = fmaf(wv.z, es, a2);
            a3 = fmaf(wv.w, es, a3);
        }
        int t = t0 + tg;
        if (t + 3 < T) {
            outb[(size_t)(tg + 0) * D_] = a0;
            outb[(size_t)(tg + 1) * D_] = a1;
            outb[(size_t)(tg + 2) * D_] = a2;
            outb[(size_t)(tg + 3) * D_] = a3;
        } else {
            float av[4] = {a0, a1, a2, a3};
            for (int i = 0; i < 4; i++)
                if (t + i < T)
                    outb[(size_t)(tg + i) * D_] = av[i];
        }
    }
}

// ---------------- single fused kernel ----------------
__global__ __launch_bounds__(256)
void gauss_fused_kernel(const void* __restrict__ text,
                        const void* __restrict__ durs,
                        const float* __restrict__ embed,
                        float* __restrict__ out, int T)
{
    __shared__ float smem[SMEM_F];
    __shared__ int   sK, stot;
    float* wsm  = smem + OFF_W;
    float* esm  = smem + OFF_E;
    float* sdur = smem + OFF_DUR;
    float* s_c  = smem + OFF_C;
    float* s_is = smem + OFF_IS;
    float* s_cf = smem + OFF_CF;
    int*   s_id = (int*)(smem + OFF_ID);

    const int b   = blockIdx.y;
    const int t0  = blockIdx.x * TT;
    const int tid = threadIdx.x;
    if (t0 >= T) return;

    // dtype detection: text values are all in [1,256); if int64 (LE), the
    // second 32-bit word is the high half of text[0] == 0; if int32 it's
    // text[0][1] >= 1.
    const bool is64 = (((const int*)text)[1] == 0);

    // ---- load durations, find K (nonzero durs form a prefix) ----
    if (tid == 0) sK = S_;
    __syncthreads();
    for (int s = tid; s < S_; s += 256) {
        long long dv = load_i(durs, b * S_ + s, is64);
        sdur[s] = (float)dv;
        if (dv == 0) atomicMin(&sK, s);
    }
    __syncthreads();
    const int K = sK;

    if (K <= KSM && K > 0) {
        // ---- serial param scan over the tiny prefix (from shared) ----
        if (tid == 0) {
            float cum = 0.0f;
            for (int k = 0; k < K; k++) {
                float df  = sdur[k];
                float sig = 0.5f * df + EPSF;
                s_c [k] = 0.5f * df + cum;
                s_is[k] = 1.0f / sig;
                s_cf[k] = INV_SQRT_2PI / sig;
                cum += df;
            }
            stot = (int)cum;
        }
        if (tid < K) s_id[tid] = (int)load_i(text, b * S_ + tid, is64);
        __syncthreads();

        // ---- phase 1: gaussian weights for the tile, s-major in shared ----
        const int items = K * TT;
        for (int idx = tid; idx < items; idx += 256) {
            int s = idx >> 7;                 // TT == 128
            int t = idx & (TT - 1);
            float tt = (float)(t0 + t) + 0.5f;
            float z  = (tt - s_c[s]) * s_is[s];
            wsm[idx] = s_cf[s] * __expf(-0.5f * z * z);
        }
        // ---- preload the K embedding rows into shared ----
        for (int idx = tid; idx < K * D_; idx += 256) {
            int s = idx >> 8;                 // D_ == 256
            esm[idx] = embed[s_id[s] * D_ + (idx & (D_ - 1))];
        }
        __syncthreads();

        // ---- fold normalization + time-invalid mask into wsm in place ----
        if (tid < TT) {
            float den = EPSF;
            for (int s = 0; s < K; s++) den += wsm[s * TT + tid];
            float r = 1.0f / den;
            if (t0 + tid >= stot) r = 0.0f;   // invalid frames -> zeros (matches ref:
                                              // last col forced to 1 but PAD embed row is 0)
            for (int s = 0; s < K; s++) wsm[s * TT + tid] *= r;
        }
        __syncthreads();

        const int d = tid;
        float* outb = out + ((size_t)b * T + t0) * D_ + d;
        switch (K) {
            case 1:  phase2<1 >(wsm, esm, outb, t0, T, d); break;
            case 2:  phase2<2 >(wsm, esm, outb, t0, T, d); break;
            case 3:  phase2<3 >(wsm, esm, outb, t0, T, d); break;
            case 4:  phase2<4 >(wsm, esm, outb, t0, T, d); break;
            case 5:  phase2<5 >(wsm, esm, outb, t0, T, d); break;
            case 6:  phase2<6 >(wsm, esm, outb, t0, T, d); break;
            case 7:  phase2<7 >(wsm, esm, outb, t0, T, d); break;
            case 8:  phase2<8 >(wsm, esm, outb, t0, T, d); break;
            case 9:  phase2<9 >(wsm, esm, outb, t0, T, d); break;
            case 10: phase2<10>(wsm, esm, outb, t0, T, d); break;
            default: phase2_gen(wsm, esm, outb, t0, T, d, K); break;
        }
    } else if (K == 0) {
        // all frames invalid -> zeros
        float* outb = out + ((size_t)b * T + t0) * D_ + tid;
        int frames = T - t0; if (frames > TT) frames = TT;
        for (int t = 0; t < frames; t++) outb[(size_t)t * D_] = 0.0f;
    } else {
        // ---- general fallback (K > KSM): alias the big shared region ----
        float* fc  = wsm;            // [S_]
        float* fis = wsm + S_;       // [S_]
        float* fcf = wsm + 2 * S_;   // [S_]
        int*   fid = (int*)(wsm + 3 * S_); // [S_]
        float* wf  = wsm + 4 * S_;   // [S_]   (5*S_ = 2560 <= KSM*(TT+D_) = 11520)

        if (tid == 0) {
            float cum = 0.0f;
            for (int k = 0; k < K; k++) {
                float df  = sdur[k];
                float sig = 0.5f * df + EPSF;
                fc [k] = 0.5f * df + cum;
                fis[k] = 1.0f / sig;
                fcf[k] = INV_SQRT_2PI / sig;
                cum += df;
            }
            stot = (int)cum;
        }
        for (int k = tid; k < K; k += 256)
            fid[k] = (int)load_i(text, b * S_ + k, is64);
        __syncthreads();
        const int total = stot;

        const int d = tid;
        for (int t = 0; t < TT; t++) {
            int tabs = t0 + t;
            if (tabs >= T) break;
            for (int s = tid; s < K; s += 256) {
                float tt = (float)tabs + 0.5f;
                float z  = (tt - fc[s]) * fis[s];
                wf[s] = fcf[s] * __expf(-0.5f * z * z);
            }
            __syncthreads();
            float den = EPSF;
            for (int s = 0; s < K; s++) den += wf[s];
            float acc = 0.f;
            for (int s = 0; s < K; s++) acc += wf[s] * embed[fid[s] * D_ + d];
            out[((size_t)b * T + tabs) * D_ + d] = (tabs < total) ? acc / den : 0.0f;
            __syncthreads();
        }
    }
}

// ---------------- launcher: ONE kernel node ----------------
extern "C" void kernel_launch(void* const* d_in, const int* in_sizes, int n_in,
                              void* d_out, int out_size)
{
    const void*  text  = d_in[0];                 // int32 or int64, detected on-device
    const void*  durs  = d_in[1];
    const float* embed = (const float*)d_in[2];
    float*       out   = (float*)d_out;

    int T = out_size / (B_ * D_);                 // derive T from output size

    dim3 grid((T + TT - 1) / TT, B_);
    gauss_fused_kernel<<<grid, 256>>>(text, durs, embed, out, T);
}